// round 15
// baseline (speedup 1.0000x reference)
#include <cuda_runtime.h>
#include <cuda_bf16.h>
#include <cstdint>

#define NN 100000
#define EE 1600000
#define ETOT (EE + NN)
#define HALF1 50048   // chunk-a node boundary (mult of 128 and 8)

// ---------------- scratch (static __device__ — no allocations) ----------------
__device__ uint32_t g_h1b[NN * 32];   // h1 as packed bf16x2 (col pairs)
__device__ uint32_t g_h2b[NN * 64];   // h2 as packed bf16x2 (col pairs)
__device__ float g_as1[NN * 8];
__device__ float g_ad1[NN * 8];
__device__ float g_as2[NN * 8];
__device__ float g_ad2[NN * 8];
__device__ int   g_rowptr[NN + 1];
__device__ int   g_cur[NN];
__device__ int   g_csr[ETOT];
__device__ int   g_bagg[98];
__device__ int   g_cnt;
__device__ __nv_bfloat16 g_w1h[64 * 512];   // W1^T bf16 [n][k]
__device__ __nv_bfloat16 g_w2h[128 * 64];   // W2^T bf16 [n][k]
__device__ __nv_bfloat16 g_o1h[NN * 64];    // out1 bf16

// ---------------- streams/events (static init, before harness checkpoints) -----
struct SideStreams {
    cudaStream_t sA;
    cudaEvent_t e0, eA, eB, eC;
    SideStreams() {
        cudaStreamCreateWithFlags(&sA, cudaStreamNonBlocking);
        cudaEventCreateWithFlags(&e0, cudaEventDisableTiming);
        cudaEventCreateWithFlags(&eA, cudaEventDisableTiming);
        cudaEventCreateWithFlags(&eB, cudaEventDisableTiming);
        cudaEventCreateWithFlags(&eC, cudaEventDisableTiming);
    }
};
static SideStreams g_ss;

// ---------------- warp mma ------------------------------------------------------
__device__ __forceinline__ void mma16816(float* c, uint32_t a0, uint32_t a1,
                                         uint32_t a2, uint32_t a3,
                                         uint32_t b0, uint32_t b1) {
    asm volatile(
        "mma.sync.aligned.m16n8k16.row.col.f32.bf16.bf16.f32 "
        "{%0,%1,%2,%3}, {%4,%5,%6,%7}, {%8,%9}, {%0,%1,%2,%3};"
        : "+f"(c[0]), "+f"(c[1]), "+f"(c[2]), "+f"(c[3])
        : "r"(a0), "r"(a1), "r"(a2), "r"(a3), "r"(b0), "r"(b1));
}

// ---------------- prep: weight bf16 split + counter resets ----------------------
__global__ void k_prep(const float* __restrict__ W1, const float* __restrict__ W2) {
    int idx = blockIdx.x * 256 + threadIdx.x;
    if (idx < NN) g_cur[idx] = 0;
    if (idx == 0) g_cnt = 0;
    if (idx < 512 * 64) {
        int k = idx >> 6, n = idx & 63;
        g_w1h[n * 512 + k] = __float2bfloat16(W1[idx]);
    }
    if (idx < 64 * 128) {
        int k = idx >> 7, n = idx & 127;
        g_w2h[n * 64 + k] = __float2bfloat16(W2[idx]);
    }
}

// ---------------- CSR build (split kernels) -------------------------------------
__global__ void k_count(const int* __restrict__ dst) {
    int e4 = blockIdx.x * blockDim.x + threadIdx.x;
    if (e4 < EE / 4) {
        int4 d = *(const int4*)(dst + e4 * 4);
        atomicAdd(&g_cur[d.x], 1);
        atomicAdd(&g_cur[d.y], 1);
        atomicAdd(&g_cur[d.z], 1);
        atomicAdd(&g_cur[d.w], 1);
    }
}
__global__ void k_scan_lb() {
    __shared__ int sh[1024];
    __shared__ int s_excl;
    int t = threadIdx.x, bid = blockIdx.x;
    int i = bid * 1024 + t;
    int v = (i < NN) ? g_cur[i] + 1 : 0;  // +1 = self loop
    sh[t] = v;
    __syncthreads();
    for (int off = 1; off < 1024; off <<= 1) {
        int a = (t >= off) ? sh[t - off] : 0;
        __syncthreads();
        sh[t] += a;
        __syncthreads();
    }
    int incl = sh[t];
    if (t == 0) {
        g_bagg[bid] = sh[1023];
        __threadfence();
        atomicAdd(&g_cnt, 1);
        while (atomicAdd(&g_cnt, 0) < 98) { }
    }
    __syncthreads();
    if (t < 32) {
        int sum = 0;
        for (int base = 0; base < bid; base += 32) {
            int idx2 = base + t;
            int val = (idx2 < bid) ? g_bagg[idx2] : 0;
#pragma unroll
            for (int o = 16; o; o >>= 1) val += __shfl_xor_sync(0xffffffffu, val, o);
            sum += val;
        }
        if (t == 0) s_excl = sum;
    }
    __syncthreads();
    if (i < NN) {
        int p = s_excl + incl - v;
        g_rowptr[i] = p;
        g_csr[p] = i;
        g_cur[i] = p + 1;
    }
    if (i == 0) g_rowptr[NN] = ETOT;
}
__global__ void k_scatter(const int* __restrict__ src, const int* __restrict__ dst) {
    int e4 = blockIdx.x * blockDim.x + threadIdx.x;
    if (e4 < EE / 4) {
        int4 s = *(const int4*)(src + e4 * 4);
        int4 d = *(const int4*)(dst + e4 * 4);
        g_csr[atomicAdd(&g_cur[d.x], 1)] = s.x;
        g_csr[atomicAdd(&g_cur[d.y], 1)] = s.y;
        g_csr[atomicAdd(&g_cur[d.z], 1)] = s.z;
        g_csr[atomicAdd(&g_cur[d.w], 1)] = s.w;
    }
}

// ---------------- layer-1 GEMM via mma.sync (pure bf16), alpha fused ------------
#define A_OFF 0
#define B_OFF 36864
#define SM1_TOTAL 73728

__global__ void __launch_bounds__(256) k_gemm1_mma(
    const float* __restrict__ x, const __nv_bfloat16* __restrict__ Wh,
    const float* __restrict__ aS, const float* __restrict__ aD) {
    extern __shared__ char smem[];
    const int tid = threadIdx.x;
    const int wid = tid >> 5, lane = tid & 31;
    const int gr = lane >> 2;
    const int kc = (lane & 3) * 2;
    const int m0 = blockIdx.x * 256;
    const int wr = wid * 32;

    float acc[2][8][4];
#pragma unroll
    for (int i = 0; i < 2; i++)
#pragma unroll
        for (int j = 0; j < 8; j++)
#pragma unroll
            for (int q = 0; q < 4; q++) acc[i][j][q] = 0.f;

    for (int kt = 0; kt < 512; kt += 64) {
#pragma unroll
        for (int i = 0; i < 16; i++) {
            int idx = tid + 256 * i;
            int r = idx >> 4, c4 = idx & 15;
            float4 v = make_float4(0.f, 0.f, 0.f, 0.f);
            if (m0 + r < NN)
                v = *(const float4*)(x + (size_t)(m0 + r) * 512 + kt + c4 * 4);
            __nv_bfloat162 h01 = __floats2bfloat162_rn(v.x, v.y);
            __nv_bfloat162 h23 = __floats2bfloat162_rn(v.z, v.w);
            *(uint2*)(smem + A_OFF + r * 144 + c4 * 8) =
                make_uint2(*(uint32_t*)&h01, *(uint32_t*)&h23);
        }
#pragma unroll
        for (int i = 0; i < 4; i++) {
            int idx = tid + 256 * i;
            int n = idx >> 4, c4 = idx & 15;
            *(uint2*)(smem + B_OFF + n * 144 + c4 * 8) =
                *(const uint2*)(Wh + n * 512 + kt + c4 * 4);
        }
        __syncthreads();
#pragma unroll
        for (int s = 0; s < 4; s++) {
            const int ks = s * 16;
            uint32_t ar[2][4];
#pragma unroll
            for (int i = 0; i < 2; i++) {
                int r0 = wr + i * 16 + gr;
                const char* pa = smem + A_OFF + (r0 * 144 + (ks + kc) * 2);
                ar[i][0] = *(const uint32_t*)(pa);
                ar[i][1] = *(const uint32_t*)(pa + 8 * 144);
                ar[i][2] = *(const uint32_t*)(pa + 16);
                ar[i][3] = *(const uint32_t*)(pa + 8 * 144 + 16);
            }
#pragma unroll
            for (int j = 0; j < 8; j++) {
                int n0 = j * 8 + gr;
                const char* pb = smem + B_OFF + (n0 * 144 + (ks + kc) * 2);
                uint32_t b0 = *(const uint32_t*)(pb);
                uint32_t b1 = *(const uint32_t*)(pb + 16);
#pragma unroll
                for (int i = 0; i < 2; i++)
                    mma16816(acc[i][j], ar[i][0], ar[i][1], ar[i][2], ar[i][3], b0, b1);
            }
        }
        __syncthreads();
    }

    float* Cs = (float*)smem;
#pragma unroll
    for (int i = 0; i < 2; i++) {
        int r0 = wr + i * 16 + gr;
#pragma unroll
        for (int j = 0; j < 8; j++) {
            int col = j * 8 + kc;
            *(float2*)&Cs[r0 * 72 + col] = make_float2(acc[i][j][0], acc[i][j][1]);
            *(float2*)&Cs[(r0 + 8) * 72 + col] = make_float2(acc[i][j][2], acc[i][j][3]);
        }
    }
    __syncthreads();

    int m = m0 + tid;
    if (m < NN) {
        const float* row = Cs + tid * 72;
#pragma unroll
        for (int c = 0; c < 64; c += 8) {
            __nv_bfloat162 t0 = __floats2bfloat162_rn(row[c + 0], row[c + 1]);
            __nv_bfloat162 t1 = __floats2bfloat162_rn(row[c + 2], row[c + 3]);
            __nv_bfloat162 t2 = __floats2bfloat162_rn(row[c + 4], row[c + 5]);
            __nv_bfloat162 t3 = __floats2bfloat162_rn(row[c + 6], row[c + 7]);
            *(uint4*)(g_h1b + (size_t)m * 32 + c / 2) =
                make_uint4(*(uint32_t*)&t0, *(uint32_t*)&t1,
                           *(uint32_t*)&t2, *(uint32_t*)&t3);
        }
        float s[8], t[8];
#pragma unroll
        for (int h = 0; h < 8; h++) { s[h] = 0.f; t[h] = 0.f; }
#pragma unroll
        for (int h = 0; h < 8; h++)
#pragma unroll
            for (int c = 0; c < 8; c++) {
                float v = row[h * 8 + c];
                s[h] = fmaf(v, aS[h * 8 + c], s[h]);
                t[h] = fmaf(v, aD[h * 8 + c], t[h]);
            }
        *(float4*)(g_as1 + (size_t)m * 8) = make_float4(s[0], s[1], s[2], s[3]);
        *(float4*)(g_as1 + (size_t)m * 8 + 4) = make_float4(s[4], s[5], s[6], s[7]);
        *(float4*)(g_ad1 + (size_t)m * 8) = make_float4(t[0], t[1], t[2], t[3]);
        *(float4*)(g_ad1 + (size_t)m * 8 + 4) = make_float4(t[4], t[5], t[6], t[7]);
    }
}

// ---------------- layer-2 GEMM via mma.sync (pure bf16), alpha fused ------------
#define G2_A 0
#define G2_B 18432
#define G2_TOTAL 67584

__global__ void __launch_bounds__(256) k_gemm2_mma(
    int mbase, int mlimit,
    const __nv_bfloat16* __restrict__ Ah, const __nv_bfloat16* __restrict__ Bh,
    const float* __restrict__ aS, const float* __restrict__ aD) {
    extern __shared__ char smem[];
    const int tid = threadIdx.x;
    const int wid = tid >> 5, lane = tid & 31;
    const int gr = lane >> 2;
    const int kc = (lane & 3) * 2;
    const int wm = wid & 3, wn = wid >> 2;
    const int m0 = mbase + blockIdx.x * 128;

#pragma unroll
    for (int i = 0; i < 8; i++) {
        int idx = tid + 256 * i;
        int r = idx >> 4, c4 = idx & 15;
        uint2 vh = make_uint2(0u, 0u);
        if (m0 + r < mlimit)
            vh = *(const uint2*)(Ah + (size_t)(m0 + r) * 64 + c4 * 4);
        *(uint2*)(smem + G2_A + r * 144 + c4 * 8) = vh;
    }
#pragma unroll
    for (int i = 0; i < 8; i++) {
        int idx = tid + 256 * i;
        int n = idx >> 4, c4 = idx & 15;
        *(uint2*)(smem + G2_B + n * 144 + c4 * 8) =
            *(const uint2*)(Bh + n * 64 + c4 * 4);
    }
    __syncthreads();

    float acc[2][8][4];
#pragma unroll
    for (int i = 0; i < 2; i++)
#pragma unroll
        for (int j = 0; j < 8; j++)
#pragma unroll
            for (int q = 0; q < 4; q++) acc[i][j][q] = 0.f;

#pragma unroll
    for (int s = 0; s < 4; s++) {
        const int ks = s * 16;
        uint32_t ar[2][4];
#pragma unroll
        for (int i = 0; i < 2; i++) {
            int r0 = wm * 32 + i * 16 + gr;
            const char* pa = smem + G2_A + (r0 * 144 + (ks + kc) * 2);
            ar[i][0] = *(const uint32_t*)(pa);
            ar[i][1] = *(const uint32_t*)(pa + 8 * 144);
            ar[i][2] = *(const uint32_t*)(pa + 16);
            ar[i][3] = *(const uint32_t*)(pa + 8 * 144 + 16);
        }
#pragma unroll
        for (int j = 0; j < 8; j++) {
            int n0 = wn * 64 + j * 8 + gr;
            const char* pb = smem + G2_B + (n0 * 144 + (ks + kc) * 2);
            uint32_t b0 = *(const uint32_t*)(pb);
            uint32_t b1 = *(const uint32_t*)(pb + 16);
#pragma unroll
            for (int i = 0; i < 2; i++)
                mma16816(acc[i][j], ar[i][0], ar[i][1], ar[i][2], ar[i][3], b0, b1);
        }
    }
    __syncthreads();

    float* Cs = (float*)smem;
#pragma unroll
    for (int i = 0; i < 2; i++) {
        int r0 = wm * 32 + i * 16 + gr;
#pragma unroll
        for (int j = 0; j < 8; j++) {
            int col = wn * 64 + j * 8 + kc;
            *(float2*)&Cs[r0 * 132 + col] = make_float2(acc[i][j][0], acc[i][j][1]);
            *(float2*)&Cs[(r0 + 8) * 132 + col] = make_float2(acc[i][j][2], acc[i][j][3]);
        }
    }
    __syncthreads();

    int r = tid >> 1, chalf = (tid & 1) * 64;
    int m = m0 + r;
    if (m < mlimit) {
        const float* row = Cs + r * 132 + chalf;
#pragma unroll
        for (int c = 0; c < 64; c += 8) {
            __nv_bfloat162 t0 = __floats2bfloat162_rn(row[c + 0], row[c + 1]);
            __nv_bfloat162 t1 = __floats2bfloat162_rn(row[c + 2], row[c + 3]);
            __nv_bfloat162 t2 = __floats2bfloat162_rn(row[c + 4], row[c + 5]);
            __nv_bfloat162 t3 = __floats2bfloat162_rn(row[c + 6], row[c + 7]);
            *(uint4*)(g_h2b + (size_t)m * 64 + (tid & 1) * 32 + c / 2) =
                make_uint4(*(uint32_t*)&t0, *(uint32_t*)&t1,
                           *(uint32_t*)&t2, *(uint32_t*)&t3);
        }
        int hb = (tid & 1) * 4;
        float s[4], t[4];
#pragma unroll
        for (int q = 0; q < 4; q++) { s[q] = 0.f; t[q] = 0.f; }
#pragma unroll
        for (int q = 0; q < 4; q++) {
            int hh = hb + q;
#pragma unroll
            for (int c = 0; c < 16; c++) {
                float v = row[q * 16 + c];
                s[q] = fmaf(v, aS[hh * 16 + c], s[q]);
                t[q] = fmaf(v, aD[hh * 16 + c], t[q]);
            }
        }
        *(float4*)(g_as2 + (size_t)m * 8 + hb) = make_float4(s[0], s[1], s[2], s[3]);
        *(float4*)(g_ad2 + (size_t)m * 8 + hb) = make_float4(t[0], t[1], t[2], t[3]);
    }
}

// ---------------- layer-1 aggregation (bf16 h1, col-pair lanes) -----------------
__global__ void __launch_bounds__(256, 6) k_agg1(
    int nbase, int nlimit,
    const float* __restrict__ bias, const float* __restrict__ preluw) {
    __shared__ float s_ex[8][32][8];
    __shared__ int s_sr[8][32];
    int warp = threadIdx.x >> 5, lane = threadIdx.x & 31;
    int n = nbase + blockIdx.x * 8 + warp;
    if (n >= nlimit) return;
    int s = g_rowptr[n], e2 = g_rowptr[n + 1];

    float adv[8];
    {
        float4 a0 = *(const float4*)(g_ad1 + n * 8);
        float4 a1 = *(const float4*)(g_ad1 + n * 8 + 4);
        adv[0] = a0.x; adv[1] = a0.y; adv[2] = a0.z; adv[3] = a0.w;
        adv[4] = a1.x; adv[5] = a1.y; adv[6] = a1.z; adv[7] = a1.w;
    }
    float den[8];
#pragma unroll
    for (int k = 0; k < 8; k++) den[k] = 0.f;
    float a0c = 0.f, a1c = 0.f;
    const int hown = lane >> 2;
    for (int base = s; base < e2; base += 32) {
        int idx = base + lane;
        int cnt = min(32, e2 - base);
        int sr = 0;
        float ex[8];
#pragma unroll
        for (int k = 0; k < 8; k++) ex[k] = 0.f;
        if (idx < e2) {
            sr = g_csr[idx];
            float4 a0 = *(const float4*)(g_as1 + sr * 8);
            float4 a1 = *(const float4*)(g_as1 + sr * 8 + 4);
            float av[8] = {a0.x, a0.y, a0.z, a0.w, a1.x, a1.y, a1.z, a1.w};
#pragma unroll
            for (int k = 0; k < 8; k++) {
                float e = av[k] + adv[k];
                e = e >= 0.f ? e : 0.2f * e;
                ex[k] = __expf(e);
                den[k] += ex[k];
            }
        }
        s_sr[warp][lane] = sr;
        *(float4*)&s_ex[warp][lane][0] = make_float4(ex[0], ex[1], ex[2], ex[3]);
        *(float4*)&s_ex[warp][lane][4] = make_float4(ex[4], ex[5], ex[6], ex[7]);
        __syncwarp();
        int cnt4 = (cnt + 3) & ~3;
        for (int j = 0; j < cnt4; j += 4) {
            int s0 = s_sr[warp][j + 0], s1 = s_sr[warp][j + 1];
            int s2 = s_sr[warp][j + 2], s3 = s_sr[warp][j + 3];
            uint32_t q0 = g_h1b[(size_t)s0 * 32 + lane];
            uint32_t q1 = g_h1b[(size_t)s1 * 32 + lane];
            uint32_t q2 = g_h1b[(size_t)s2 * 32 + lane];
            uint32_t q3 = g_h1b[(size_t)s3 * 32 + lane];
            float e0 = s_ex[warp][j + 0][hown];
            float e1 = s_ex[warp][j + 1][hown];
            float e2w = s_ex[warp][j + 2][hown];
            float e3 = s_ex[warp][j + 3][hown];
            float2 f0 = __bfloat1622float2(*(__nv_bfloat162*)&q0);
            float2 f1 = __bfloat1622float2(*(__nv_bfloat162*)&q1);
            float2 f2 = __bfloat1622float2(*(__nv_bfloat162*)&q2);
            float2 f3 = __bfloat1622float2(*(__nv_bfloat162*)&q3);
            a0c = fmaf(e0, f0.x, a0c); a1c = fmaf(e0, f0.y, a1c);
            a0c = fmaf(e1, f1.x, a0c); a1c = fmaf(e1, f1.y, a1c);
            a0c = fmaf(e2w, f2.x, a0c); a1c = fmaf(e2w, f2.y, a1c);
            a0c = fmaf(e3, f3.x, a0c); a1c = fmaf(e3, f3.y, a1c);
        }
        __syncwarp();
    }
#pragma unroll
    for (int k = 0; k < 8; k++)
#pragma unroll
        for (int off = 16; off; off >>= 1)
            den[k] += __shfl_xor_sync(0xffffffffu, den[k], off);

    float d = (hown == 0) ? den[0] : (hown == 1) ? den[1] : (hown == 2) ? den[2]
            : (hown == 3) ? den[3] : (hown == 4) ? den[4] : (hown == 5) ? den[5]
            : (hown == 6) ? den[6] : den[7];
    float pw = *preluw;
    float v0 = a0c / d + bias[2 * lane];
    float v1 = a1c / d + bias[2 * lane + 1];
    v0 = v0 >= 0.f ? v0 : pw * v0;
    v1 = v1 >= 0.f ? v1 : pw * v1;
    __nv_bfloat162 hi = __floats2bfloat162_rn(v0, v1);
    ((uint32_t*)(g_o1h + (size_t)n * 64))[lane] = *(uint32_t*)&hi;
}

// ---------------- layer-2 aggregation (bf16 h2) + mean + bias + log_softmax -----
__global__ void __launch_bounds__(256, 6) k_agg2(
    const float* __restrict__ bias2, float* __restrict__ out) {
    __shared__ float s_ex[8][32][8];
    __shared__ int s_sr[8][32];
    int warp = threadIdx.x >> 5, lane = threadIdx.x & 31;
    int n = blockIdx.x * 8 + warp;
    if (n >= NN) return;
    int s = g_rowptr[n], e2 = g_rowptr[n + 1];

    float adv[8];
    {
        float4 a0 = *(const float4*)(g_ad2 + n * 8);
        float4 a1 = *(const float4*)(g_ad2 + n * 8 + 4);
        adv[0] = a0.x; adv[1] = a0.y; adv[2] = a0.z; adv[3] = a0.w;
        adv[4] = a1.x; adv[5] = a1.y; adv[6] = a1.z; adv[7] = a1.w;
    }
    float den[8];
#pragma unroll
    for (int k = 0; k < 8; k++) den[k] = 0.f;
    float a00 = 0.f, a01 = 0.f, a10 = 0.f, a11 = 0.f;
    const int ha = lane >> 3, hb = 4 + (lane >> 3);
    for (int base = s; base < e2; base += 32) {
        int idx = base + lane;
        int cnt = min(32, e2 - base);
        int sr = 0;
        float ex[8];
#pragma unroll
        for (int k = 0; k < 8; k++) ex[k] = 0.f;
        if (idx < e2) {
            sr = g_csr[idx];
            float4 a0 = *(const float4*)(g_as2 + sr * 8);
            float4 a1 = *(const float4*)(g_as2 + sr * 8 + 4);
            float av[8] = {a0.x, a0.y, a0.z, a0.w, a1.x, a1.y, a1.z, a1.w};
#pragma unroll
            for (int k = 0; k < 8; k++) {
                float e = av[k] + adv[k];
                e = e >= 0.f ? e : 0.2f * e;
                ex[k] = __expf(e);
                den[k] += ex[k];
            }
        }
        s_sr[warp][lane] = sr;
        *(float4*)&s_ex[warp][lane][0] = make_float4(ex[0], ex[1], ex[2], ex[3]);
        *(float4*)&s_ex[warp][lane][4] = make_float4(ex[4], ex[5], ex[6], ex[7]);
        __syncwarp();
        int cnt4 = (cnt + 3) & ~3;
        for (int j = 0; j < cnt4; j += 4) {
            int s0 = s_sr[warp][j + 0], s1 = s_sr[warp][j + 1];
            int s2 = s_sr[warp][j + 2], s3 = s_sr[warp][j + 3];
            const uint32_t* p0 = g_h2b + (size_t)s0 * 64;
            const uint32_t* p1 = g_h2b + (size_t)s1 * 64;
            const uint32_t* p2 = g_h2b + (size_t)s2 * 64;
            const uint32_t* p3 = g_h2b + (size_t)s3 * 64;
            uint32_t qa0 = p0[lane], qb0 = p0[lane + 32];
            uint32_t qa1 = p1[lane], qb1 = p1[lane + 32];
            uint32_t qa2 = p2[lane], qb2 = p2[lane + 32];
            uint32_t qa3 = p3[lane], qb3 = p3[lane + 32];
            float ea0 = s_ex[warp][j + 0][ha], eb0 = s_ex[warp][j + 0][hb];
            float ea1 = s_ex[warp][j + 1][ha], eb1 = s_ex[warp][j + 1][hb];
            float ea2 = s_ex[warp][j + 2][ha], eb2 = s_ex[warp][j + 2][hb];
            float ea3 = s_ex[warp][j + 3][ha], eb3 = s_ex[warp][j + 3][hb];
            float2 fa0 = __bfloat1622float2(*(__nv_bfloat162*)&qa0);
            float2 fb0 = __bfloat1622float2(*(__nv_bfloat162*)&qb0);
            float2 fa1 = __bfloat1622float2(*(__nv_bfloat162*)&qa1);
            float2 fb1 = __bfloat1622float2(*(__nv_bfloat162*)&qb1);
            float2 fa2 = __bfloat1622float2(*(__nv_bfloat162*)&qa2);
            float2 fb2 = __bfloat1622float2(*(__nv_bfloat162*)&qb2);
            float2 fa3 = __bfloat1622float2(*(__nv_bfloat162*)&qa3);
            float2 fb3 = __bfloat1622float2(*(__nv_bfloat162*)&qb3);
            a00 = fmaf(ea0, fa0.x, a00); a01 = fmaf(ea0, fa0.y, a01);
            a10 = fmaf(eb0, fb0.x, a10); a11 = fmaf(eb0, fb0.y, a11);
            a00 = fmaf(ea1, fa1.x, a00); a01 = fmaf(ea1, fa1.y, a01);
            a10 = fmaf(eb1, fb1.x, a10); a11 = fmaf(eb1, fb1.y, a11);
            a00 = fmaf(ea2, fa2.x, a00); a01 = fmaf(ea2, fa2.y, a01);
            a10 = fmaf(eb2, fb2.x, a10); a11 = fmaf(eb2, fb2.y, a11);
            a00 = fmaf(ea3, fa3.x, a00); a01 = fmaf(ea3, fa3.y, a01);
            a10 = fmaf(eb3, fb3.x, a10); a11 = fmaf(eb3, fb3.y, a11);
        }
        __syncwarp();
    }
#pragma unroll
    for (int k = 0; k < 8; k++)
#pragma unroll
        for (int off = 16; off; off >>= 1)
            den[k] += __shfl_xor_sync(0xffffffffu, den[k], off);

    float da = (lane < 8) ? den[0] : (lane < 16) ? den[1] : (lane < 24) ? den[2] : den[3];
    float db = (lane < 8) ? den[4] : (lane < 16) ? den[5] : (lane < 24) ? den[6] : den[7];
    float v0 = a00 / da + a10 / db;
    float v1 = a01 / da + a11 / db;
    v0 += __shfl_xor_sync(0xffffffffu, v0, 8);
    v0 += __shfl_xor_sync(0xffffffffu, v0, 16);
    v1 += __shfl_xor_sync(0xffffffffu, v1, 8);
    v1 += __shfl_xor_sync(0xffffffffu, v1, 16);
    int cp = lane & 7;
    v0 = v0 * 0.125f + bias2[2 * cp];
    v1 = v1 * 0.125f + bias2[2 * cp + 1];
    float mx = fmaxf(v0, v1);
#pragma unroll
    for (int off = 4; off; off >>= 1) mx = fmaxf(mx, __shfl_xor_sync(0xffffffffu, mx, off));
    float se = __expf(v0 - mx) + __expf(v1 - mx);
#pragma unroll
    for (int off = 4; off; off >>= 1) se += __shfl_xor_sync(0xffffffffu, se, off);
    float ls = __logf(se);
    if (lane < 8)
        *(float2*)(out + (size_t)n * 16 + 2 * cp) =
            make_float2(v0 - mx - ls, v1 - mx - ls);
}

// ---------------- launcher ------------------------------------------------------
extern "C" void kernel_launch(void* const* d_in, const int* in_sizes, int n_in,
                              void* d_out, int out_size) {
    const float* x   = (const float*)d_in[0];
    const int*   ei  = (const int*)d_in[1];
    const float* W1  = (const float*)d_in[2];
    const float* aS1 = (const float*)d_in[3];
    const float* aD1 = (const float*)d_in[4];
    const float* b1  = (const float*)d_in[5];
    const float* pw  = (const float*)d_in[6];
    const float* W2  = (const float*)d_in[7];
    const float* aS2 = (const float*)d_in[8];
    const float* aD2 = (const float*)d_in[9];
    const float* b2  = (const float*)d_in[10];
    float* out = (float*)d_out;

    const int* srcp = ei;
    const int* dstp = ei + EE;

    __nv_bfloat16 *p_w1h, *p_w2h, *p_o1h;
    cudaGetSymbolAddress((void**)&p_w1h, g_w1h);
    cudaGetSymbolAddress((void**)&p_w2h, g_w2h);
    cudaGetSymbolAddress((void**)&p_o1h, g_o1h);

    cudaFuncSetAttribute(k_gemm1_mma, cudaFuncAttributeMaxDynamicSharedMemorySize,
                         SM1_TOTAL);
    cudaFuncSetAttribute(k_gemm2_mma, cudaFuncAttributeMaxDynamicSharedMemorySize,
                         G2_TOTAL);

    // 1: prep (weights bf16 + counter resets)
    k_prep<<<(NN + 255) / 256, 256>>>(W1, W2);

    // fork: GEMM1 on side stream, split CSR build on default stream
    cudaEventRecord(g_ss.e0, 0);
    cudaStreamWaitEvent(g_ss.sA, g_ss.e0, 0);
    k_gemm1_mma<<<(NN + 255) / 256, 256, SM1_TOTAL, g_ss.sA>>>(x, p_w1h, aS1, aD1);
    cudaEventRecord(g_ss.eA, g_ss.sA);

    k_count<<<(EE / 4 + 255) / 256, 256>>>(dstp);
    k_scan_lb<<<98, 1024>>>();
    k_scatter<<<(EE / 4 + 255) / 256, 256>>>(srcp, dstp);

    // join, then pipelined agg1/gemm2 halves:
    cudaStreamWaitEvent(0, g_ss.eA, 0);
    k_agg1<<<HALF1 / 8, 256>>>(0, HALF1, b1, pw);                  // agg1_a
    cudaEventRecord(g_ss.eB, 0);
    k_agg1<<<(NN - HALF1 + 7) / 8, 256>>>(HALF1, NN, b1, pw);      // agg1_b
    // gemm2_a on side stream, concurrent with agg1_b
    cudaStreamWaitEvent(g_ss.sA, g_ss.eB, 0);
    k_gemm2_mma<<<HALF1 / 128, 256, G2_TOTAL, g_ss.sA>>>(0, HALF1, p_o1h, p_w2h,
                                                         aS2, aD2);
    cudaEventRecord(g_ss.eC, g_ss.sA);
    // gemm2_b on default stream (after agg1_b in program order)
    k_gemm2_mma<<<(NN - HALF1 + 127) / 128, 256, G2_TOTAL>>>(HALF1, NN, p_o1h,
                                                             p_w2h, aS2, aD2);
    cudaStreamWaitEvent(0, g_ss.eC, 0);
    k_agg2<<<(NN + 7) / 8, 256>>>(b2, out);
}

// round 16
// speedup vs baseline: 1.0550x; 1.0550x over previous
#include <cuda_runtime.h>
#include <cuda_bf16.h>
#include <cstdint>

#define NN 100000
#define EE 1600000
#define ETOT (EE + NN)
#define HALF1 50048   // chunk-a node boundary (mult of 128 and 8)

// ---------------- scratch (static __device__ — no allocations) ----------------
__device__ uint32_t g_h1b[NN * 32];   // h1 as packed bf16x2 (col pairs)
__device__ uint32_t g_h2b[NN * 64];   // h2 as packed bf16x2 (col pairs)
__device__ float g_as1[NN * 8];
__device__ float g_ad1[NN * 8];
__device__ float g_as2[NN * 8];
__device__ float g_ad2[NN * 8];
__device__ int   g_rowptr[NN + 1];
__device__ int   g_cur[NN];
__device__ int   g_csr[ETOT];
__device__ int   g_bagg[98];
__device__ int   g_cnt;
__device__ __nv_bfloat16 g_w1h[64 * 512];   // W1^T bf16 [n][k]
__device__ __nv_bfloat16 g_w2h[128 * 64];   // W2^T bf16 [n][k]
__device__ __nv_bfloat16 g_o1h[NN * 64];    // out1 bf16

// ---------------- streams/events (static init, before harness checkpoints) -----
struct SideStreams {
    cudaStream_t sA;
    cudaEvent_t e0, eA, eB, eC;
    SideStreams() {
        cudaStreamCreateWithFlags(&sA, cudaStreamNonBlocking);
        cudaEventCreateWithFlags(&e0, cudaEventDisableTiming);
        cudaEventCreateWithFlags(&eA, cudaEventDisableTiming);
        cudaEventCreateWithFlags(&eB, cudaEventDisableTiming);
        cudaEventCreateWithFlags(&eC, cudaEventDisableTiming);
    }
};
static SideStreams g_ss;

// ---------------- warp mma ------------------------------------------------------
__device__ __forceinline__ void mma16816(float* c, uint32_t a0, uint32_t a1,
                                         uint32_t a2, uint32_t a3,
                                         uint32_t b0, uint32_t b1) {
    asm volatile(
        "mma.sync.aligned.m16n8k16.row.col.f32.bf16.bf16.f32 "
        "{%0,%1,%2,%3}, {%4,%5,%6,%7}, {%8,%9}, {%0,%1,%2,%3};"
        : "+f"(c[0]), "+f"(c[1]), "+f"(c[2]), "+f"(c[3])
        : "r"(a0), "r"(a1), "r"(a2), "r"(a3), "r"(b0), "r"(b1));
}

// ---------------- prep: weight bf16 split + counter resets ----------------------
__global__ void k_prep(const float* __restrict__ W1, const float* __restrict__ W2) {
    int idx = blockIdx.x * 256 + threadIdx.x;
    if (idx < NN) g_cur[idx] = 0;
    if (idx == 0) g_cnt = 0;
    if (idx < 512 * 64) {
        int k = idx >> 6, n = idx & 63;
        g_w1h[n * 512 + k] = __float2bfloat16(W1[idx]);
    }
    if (idx < 64 * 128) {
        int k = idx >> 7, n = idx & 127;
        g_w2h[n * 64 + k] = __float2bfloat16(W2[idx]);
    }
}

// ---------------- CSR build (split kernels) -------------------------------------
__global__ void k_count(const int* __restrict__ dst) {
    int e4 = blockIdx.x * blockDim.x + threadIdx.x;
    if (e4 < EE / 4) {
        int4 d = *(const int4*)(dst + e4 * 4);
        atomicAdd(&g_cur[d.x], 1);
        atomicAdd(&g_cur[d.y], 1);
        atomicAdd(&g_cur[d.z], 1);
        atomicAdd(&g_cur[d.w], 1);
    }
}
__global__ void k_scan_lb() {
    __shared__ int sh[1024];
    __shared__ int s_excl;
    int t = threadIdx.x, bid = blockIdx.x;
    int i = bid * 1024 + t;
    int v = (i < NN) ? g_cur[i] + 1 : 0;  // +1 = self loop
    sh[t] = v;
    __syncthreads();
    for (int off = 1; off < 1024; off <<= 1) {
        int a = (t >= off) ? sh[t - off] : 0;
        __syncthreads();
        sh[t] += a;
        __syncthreads();
    }
    int incl = sh[t];
    if (t == 0) {
        g_bagg[bid] = sh[1023];
        __threadfence();
        atomicAdd(&g_cnt, 1);
        while (atomicAdd(&g_cnt, 0) < 98) { }
    }
    __syncthreads();
    if (t < 32) {
        int sum = 0;
        for (int base = 0; base < bid; base += 32) {
            int idx2 = base + t;
            int val = (idx2 < bid) ? g_bagg[idx2] : 0;
#pragma unroll
            for (int o = 16; o; o >>= 1) val += __shfl_xor_sync(0xffffffffu, val, o);
            sum += val;
        }
        if (t == 0) s_excl = sum;
    }
    __syncthreads();
    if (i < NN) {
        int p = s_excl + incl - v;
        g_rowptr[i] = p;
        g_csr[p] = i;
        g_cur[i] = p + 1;
    }
    if (i == 0) g_rowptr[NN] = ETOT;
}
__global__ void k_scatter(const int* __restrict__ src, const int* __restrict__ dst) {
    int e4 = blockIdx.x * blockDim.x + threadIdx.x;
    if (e4 < EE / 4) {
        int4 s = *(const int4*)(src + e4 * 4);
        int4 d = *(const int4*)(dst + e4 * 4);
        g_csr[atomicAdd(&g_cur[d.x], 1)] = s.x;
        g_csr[atomicAdd(&g_cur[d.y], 1)] = s.y;
        g_csr[atomicAdd(&g_cur[d.z], 1)] = s.z;
        g_csr[atomicAdd(&g_cur[d.w], 1)] = s.w;
    }
}

// ---------------- layer-1 GEMM via mma.sync (pure bf16), alpha fused ------------
#define A_OFF 0
#define B_OFF 36864
#define SM1_TOTAL 73728

__global__ void __launch_bounds__(256) k_gemm1_mma(
    const float* __restrict__ x, const __nv_bfloat16* __restrict__ Wh,
    const float* __restrict__ aS, const float* __restrict__ aD) {
    extern __shared__ char smem[];
    const int tid = threadIdx.x;
    const int wid = tid >> 5, lane = tid & 31;
    const int gr = lane >> 2;
    const int kc = (lane & 3) * 2;
    const int m0 = blockIdx.x * 256;
    const int wr = wid * 32;

    float acc[2][8][4];
#pragma unroll
    for (int i = 0; i < 2; i++)
#pragma unroll
        for (int j = 0; j < 8; j++)
#pragma unroll
            for (int q = 0; q < 4; q++) acc[i][j][q] = 0.f;

    for (int kt = 0; kt < 512; kt += 64) {
#pragma unroll
        for (int i = 0; i < 16; i++) {
            int idx = tid + 256 * i;
            int r = idx >> 4, c4 = idx & 15;
            float4 v = make_float4(0.f, 0.f, 0.f, 0.f);
            if (m0 + r < NN)
                v = *(const float4*)(x + (size_t)(m0 + r) * 512 + kt + c4 * 4);
            __nv_bfloat162 h01 = __floats2bfloat162_rn(v.x, v.y);
            __nv_bfloat162 h23 = __floats2bfloat162_rn(v.z, v.w);
            *(uint2*)(smem + A_OFF + r * 144 + c4 * 8) =
                make_uint2(*(uint32_t*)&h01, *(uint32_t*)&h23);
        }
#pragma unroll
        for (int i = 0; i < 4; i++) {
            int idx = tid + 256 * i;
            int n = idx >> 4, c4 = idx & 15;
            *(uint2*)(smem + B_OFF + n * 144 + c4 * 8) =
                *(const uint2*)(Wh + n * 512 + kt + c4 * 4);
        }
        __syncthreads();
#pragma unroll
        for (int s = 0; s < 4; s++) {
            const int ks = s * 16;
            uint32_t ar[2][4];
#pragma unroll
            for (int i = 0; i < 2; i++) {
                int r0 = wr + i * 16 + gr;
                const char* pa = smem + A_OFF + (r0 * 144 + (ks + kc) * 2);
                ar[i][0] = *(const uint32_t*)(pa);
                ar[i][1] = *(const uint32_t*)(pa + 8 * 144);
                ar[i][2] = *(const uint32_t*)(pa + 16);
                ar[i][3] = *(const uint32_t*)(pa + 8 * 144 + 16);
            }
#pragma unroll
            for (int j = 0; j < 8; j++) {
                int n0 = j * 8 + gr;
                const char* pb = smem + B_OFF + (n0 * 144 + (ks + kc) * 2);
                uint32_t b0 = *(const uint32_t*)(pb);
                uint32_t b1 = *(const uint32_t*)(pb + 16);
#pragma unroll
                for (int i = 0; i < 2; i++)
                    mma16816(acc[i][j], ar[i][0], ar[i][1], ar[i][2], ar[i][3], b0, b1);
            }
        }
        __syncthreads();
    }

    float* Cs = (float*)smem;
#pragma unroll
    for (int i = 0; i < 2; i++) {
        int r0 = wr + i * 16 + gr;
#pragma unroll
        for (int j = 0; j < 8; j++) {
            int col = j * 8 + kc;
            *(float2*)&Cs[r0 * 72 + col] = make_float2(acc[i][j][0], acc[i][j][1]);
            *(float2*)&Cs[(r0 + 8) * 72 + col] = make_float2(acc[i][j][2], acc[i][j][3]);
        }
    }
    __syncthreads();

    int m = m0 + tid;
    if (m < NN) {
        const float* row = Cs + tid * 72;
#pragma unroll
        for (int c = 0; c < 64; c += 8) {
            __nv_bfloat162 t0 = __floats2bfloat162_rn(row[c + 0], row[c + 1]);
            __nv_bfloat162 t1 = __floats2bfloat162_rn(row[c + 2], row[c + 3]);
            __nv_bfloat162 t2 = __floats2bfloat162_rn(row[c + 4], row[c + 5]);
            __nv_bfloat162 t3 = __floats2bfloat162_rn(row[c + 6], row[c + 7]);
            *(uint4*)(g_h1b + (size_t)m * 32 + c / 2) =
                make_uint4(*(uint32_t*)&t0, *(uint32_t*)&t1,
                           *(uint32_t*)&t2, *(uint32_t*)&t3);
        }
        float s[8], t[8];
#pragma unroll
        for (int h = 0; h < 8; h++) { s[h] = 0.f; t[h] = 0.f; }
#pragma unroll
        for (int h = 0; h < 8; h++)
#pragma unroll
            for (int c = 0; c < 8; c++) {
                float v = row[h * 8 + c];
                s[h] = fmaf(v, aS[h * 8 + c], s[h]);
                t[h] = fmaf(v, aD[h * 8 + c], t[h]);
            }
        *(float4*)(g_as1 + (size_t)m * 8) = make_float4(s[0], s[1], s[2], s[3]);
        *(float4*)(g_as1 + (size_t)m * 8 + 4) = make_float4(s[4], s[5], s[6], s[7]);
        *(float4*)(g_ad1 + (size_t)m * 8) = make_float4(t[0], t[1], t[2], t[3]);
        *(float4*)(g_ad1 + (size_t)m * 8 + 4) = make_float4(t[4], t[5], t[6], t[7]);
    }
}

// ---------------- layer-2 GEMM via mma.sync (pure bf16), alpha fused ------------
#define G2_A 0
#define G2_B 18432
#define G2_TOTAL 67584

__global__ void __launch_bounds__(256) k_gemm2_mma(
    int mbase, int mlimit,
    const __nv_bfloat16* __restrict__ Ah, const __nv_bfloat16* __restrict__ Bh,
    const float* __restrict__ aS, const float* __restrict__ aD) {
    extern __shared__ char smem[];
    const int tid = threadIdx.x;
    const int wid = tid >> 5, lane = tid & 31;
    const int gr = lane >> 2;
    const int kc = (lane & 3) * 2;
    const int wm = wid & 3, wn = wid >> 2;
    const int m0 = mbase + blockIdx.x * 128;

#pragma unroll
    for (int i = 0; i < 8; i++) {
        int idx = tid + 256 * i;
        int r = idx >> 4, c4 = idx & 15;
        uint2 vh = make_uint2(0u, 0u);
        if (m0 + r < mlimit)
            vh = *(const uint2*)(Ah + (size_t)(m0 + r) * 64 + c4 * 4);
        *(uint2*)(smem + G2_A + r * 144 + c4 * 8) = vh;
    }
#pragma unroll
    for (int i = 0; i < 8; i++) {
        int idx = tid + 256 * i;
        int n = idx >> 4, c4 = idx & 15;
        *(uint2*)(smem + G2_B + n * 144 + c4 * 8) =
            *(const uint2*)(Bh + n * 64 + c4 * 4);
    }
    __syncthreads();

    float acc[2][8][4];
#pragma unroll
    for (int i = 0; i < 2; i++)
#pragma unroll
        for (int j = 0; j < 8; j++)
#pragma unroll
            for (int q = 0; q < 4; q++) acc[i][j][q] = 0.f;

#pragma unroll
    for (int s = 0; s < 4; s++) {
        const int ks = s * 16;
        uint32_t ar[2][4];
#pragma unroll
        for (int i = 0; i < 2; i++) {
            int r0 = wm * 32 + i * 16 + gr;
            const char* pa = smem + G2_A + (r0 * 144 + (ks + kc) * 2);
            ar[i][0] = *(const uint32_t*)(pa);
            ar[i][1] = *(const uint32_t*)(pa + 8 * 144);
            ar[i][2] = *(const uint32_t*)(pa + 16);
            ar[i][3] = *(const uint32_t*)(pa + 8 * 144 + 16);
        }
#pragma unroll
        for (int j = 0; j < 8; j++) {
            int n0 = wn * 64 + j * 8 + gr;
            const char* pb = smem + G2_B + (n0 * 144 + (ks + kc) * 2);
            uint32_t b0 = *(const uint32_t*)(pb);
            uint32_t b1 = *(const uint32_t*)(pb + 16);
#pragma unroll
            for (int i = 0; i < 2; i++)
                mma16816(acc[i][j], ar[i][0], ar[i][1], ar[i][2], ar[i][3], b0, b1);
        }
    }
    __syncthreads();

    float* Cs = (float*)smem;
#pragma unroll
    for (int i = 0; i < 2; i++) {
        int r0 = wm * 32 + i * 16 + gr;
#pragma unroll
        for (int j = 0; j < 8; j++) {
            int col = wn * 64 + j * 8 + kc;
            *(float2*)&Cs[r0 * 132 + col] = make_float2(acc[i][j][0], acc[i][j][1]);
            *(float2*)&Cs[(r0 + 8) * 132 + col] = make_float2(acc[i][j][2], acc[i][j][3]);
        }
    }
    __syncthreads();

    int r = tid >> 1, chalf = (tid & 1) * 64;
    int m = m0 + r;
    if (m < mlimit) {
        const float* row = Cs + r * 132 + chalf;
#pragma unroll
        for (int c = 0; c < 64; c += 8) {
            __nv_bfloat162 t0 = __floats2bfloat162_rn(row[c + 0], row[c + 1]);
            __nv_bfloat162 t1 = __floats2bfloat162_rn(row[c + 2], row[c + 3]);
            __nv_bfloat162 t2 = __floats2bfloat162_rn(row[c + 4], row[c + 5]);
            __nv_bfloat162 t3 = __floats2bfloat162_rn(row[c + 6], row[c + 7]);
            *(uint4*)(g_h2b + (size_t)m * 64 + (tid & 1) * 32 + c / 2) =
                make_uint4(*(uint32_t*)&t0, *(uint32_t*)&t1,
                           *(uint32_t*)&t2, *(uint32_t*)&t3);
        }
        int hb = (tid & 1) * 4;
        float s[4], t[4];
#pragma unroll
        for (int q = 0; q < 4; q++) { s[q] = 0.f; t[q] = 0.f; }
#pragma unroll
        for (int q = 0; q < 4; q++) {
            int hh = hb + q;
#pragma unroll
            for (int c = 0; c < 16; c++) {
                float v = row[q * 16 + c];
                s[q] = fmaf(v, aS[hh * 16 + c], s[q]);
                t[q] = fmaf(v, aD[hh * 16 + c], t[q]);
            }
        }
        *(float4*)(g_as2 + (size_t)m * 8 + hb) = make_float4(s[0], s[1], s[2], s[3]);
        *(float4*)(g_ad2 + (size_t)m * 8 + hb) = make_float4(t[0], t[1], t[2], t[3]);
    }
}

// ---------------- layer-1 aggregation (bf16 h1, col-pair lanes) -----------------
__global__ void __launch_bounds__(256) k_agg1(
    int nbase, int nlimit,
    const float* __restrict__ bias, const float* __restrict__ preluw) {
    __shared__ float s_ex[8][32][8];
    __shared__ int s_sr[8][32];
    int warp = threadIdx.x >> 5, lane = threadIdx.x & 31;
    int n = nbase + blockIdx.x * 8 + warp;
    if (n >= nlimit) return;
    int s = g_rowptr[n], e2 = g_rowptr[n + 1];

    float adv[8];
    {
        float4 a0 = *(const float4*)(g_ad1 + n * 8);
        float4 a1 = *(const float4*)(g_ad1 + n * 8 + 4);
        adv[0] = a0.x; adv[1] = a0.y; adv[2] = a0.z; adv[3] = a0.w;
        adv[4] = a1.x; adv[5] = a1.y; adv[6] = a1.z; adv[7] = a1.w;
    }
    float den[8];
#pragma unroll
    for (int k = 0; k < 8; k++) den[k] = 0.f;
    float a0c = 0.f, a1c = 0.f;
    const int hown = lane >> 2;
    for (int base = s; base < e2; base += 32) {
        int idx = base + lane;
        int cnt = min(32, e2 - base);
        int sr = 0;
        float ex[8];
#pragma unroll
        for (int k = 0; k < 8; k++) ex[k] = 0.f;
        if (idx < e2) {
            sr = g_csr[idx];
            float4 a0 = *(const float4*)(g_as1 + sr * 8);
            float4 a1 = *(const float4*)(g_as1 + sr * 8 + 4);
            float av[8] = {a0.x, a0.y, a0.z, a0.w, a1.x, a1.y, a1.z, a1.w};
#pragma unroll
            for (int k = 0; k < 8; k++) {
                float e = av[k] + adv[k];
                e = e >= 0.f ? e : 0.2f * e;
                ex[k] = __expf(e);
                den[k] += ex[k];
            }
        }
        s_sr[warp][lane] = sr;
        *(float4*)&s_ex[warp][lane][0] = make_float4(ex[0], ex[1], ex[2], ex[3]);
        *(float4*)&s_ex[warp][lane][4] = make_float4(ex[4], ex[5], ex[6], ex[7]);
        __syncwarp();
        int cnt4 = (cnt + 3) & ~3;
        for (int j = 0; j < cnt4; j += 4) {
            int s0 = s_sr[warp][j + 0], s1 = s_sr[warp][j + 1];
            int s2 = s_sr[warp][j + 2], s3 = s_sr[warp][j + 3];
            uint32_t q0 = g_h1b[(size_t)s0 * 32 + lane];
            uint32_t q1 = g_h1b[(size_t)s1 * 32 + lane];
            uint32_t q2 = g_h1b[(size_t)s2 * 32 + lane];
            uint32_t q3 = g_h1b[(size_t)s3 * 32 + lane];
            float e0 = s_ex[warp][j + 0][hown];
            float e1 = s_ex[warp][j + 1][hown];
            float e2w = s_ex[warp][j + 2][hown];
            float e3 = s_ex[warp][j + 3][hown];
            float2 f0 = __bfloat1622float2(*(__nv_bfloat162*)&q0);
            float2 f1 = __bfloat1622float2(*(__nv_bfloat162*)&q1);
            float2 f2 = __bfloat1622float2(*(__nv_bfloat162*)&q2);
            float2 f3 = __bfloat1622float2(*(__nv_bfloat162*)&q3);
            a0c = fmaf(e0, f0.x, a0c); a1c = fmaf(e0, f0.y, a1c);
            a0c = fmaf(e1, f1.x, a0c); a1c = fmaf(e1, f1.y, a1c);
            a0c = fmaf(e2w, f2.x, a0c); a1c = fmaf(e2w, f2.y, a1c);
            a0c = fmaf(e3, f3.x, a0c); a1c = fmaf(e3, f3.y, a1c);
        }
        __syncwarp();
    }
#pragma unroll
    for (int k = 0; k < 8; k++)
#pragma unroll
        for (int off = 16; off; off >>= 1)
            den[k] += __shfl_xor_sync(0xffffffffu, den[k], off);

    float d = (hown == 0) ? den[0] : (hown == 1) ? den[1] : (hown == 2) ? den[2]
            : (hown == 3) ? den[3] : (hown == 4) ? den[4] : (hown == 5) ? den[5]
            : (hown == 6) ? den[6] : den[7];
    float pw = *preluw;
    float v0 = a0c / d + bias[2 * lane];
    float v1 = a1c / d + bias[2 * lane + 1];
    v0 = v0 >= 0.f ? v0 : pw * v0;
    v1 = v1 >= 0.f ? v1 : pw * v1;
    __nv_bfloat162 hi = __floats2bfloat162_rn(v0, v1);
    ((uint32_t*)(g_o1h + (size_t)n * 64))[lane] = *(uint32_t*)&hi;
}

// ---------------- layer-2 aggregation (bf16 h2) + mean + bias + log_softmax -----
__global__ void __launch_bounds__(256) k_agg2(
    const float* __restrict__ bias2, float* __restrict__ out) {
    __shared__ float s_ex[8][32][8];
    __shared__ int s_sr[8][32];
    int warp = threadIdx.x >> 5, lane = threadIdx.x & 31;
    int n = blockIdx.x * 8 + warp;
    if (n >= NN) return;
    int s = g_rowptr[n], e2 = g_rowptr[n + 1];

    float adv[8];
    {
        float4 a0 = *(const float4*)(g_ad2 + n * 8);
        float4 a1 = *(const float4*)(g_ad2 + n * 8 + 4);
        adv[0] = a0.x; adv[1] = a0.y; adv[2] = a0.z; adv[3] = a0.w;
        adv[4] = a1.x; adv[5] = a1.y; adv[6] = a1.z; adv[7] = a1.w;
    }
    float den[8];
#pragma unroll
    for (int k = 0; k < 8; k++) den[k] = 0.f;
    float a00 = 0.f, a01 = 0.f, a10 = 0.f, a11 = 0.f;
    const int ha = lane >> 3, hb = 4 + (lane >> 3);
    for (int base = s; base < e2; base += 32) {
        int idx = base + lane;
        int cnt = min(32, e2 - base);
        int sr = 0;
        float ex[8];
#pragma unroll
        for (int k = 0; k < 8; k++) ex[k] = 0.f;
        if (idx < e2) {
            sr = g_csr[idx];
            float4 a0 = *(const float4*)(g_as2 + sr * 8);
            float4 a1 = *(const float4*)(g_as2 + sr * 8 + 4);
            float av[8] = {a0.x, a0.y, a0.z, a0.w, a1.x, a1.y, a1.z, a1.w};
#pragma unroll
            for (int k = 0; k < 8; k++) {
                float e = av[k] + adv[k];
                e = e >= 0.f ? e : 0.2f * e;
                ex[k] = __expf(e);
                den[k] += ex[k];
            }
        }
        s_sr[warp][lane] = sr;
        *(float4*)&s_ex[warp][lane][0] = make_float4(ex[0], ex[1], ex[2], ex[3]);
        *(float4*)&s_ex[warp][lane][4] = make_float4(ex[4], ex[5], ex[6], ex[7]);
        __syncwarp();
        int cnt4 = (cnt + 3) & ~3;
        for (int j = 0; j < cnt4; j += 4) {
            int s0 = s_sr[warp][j + 0], s1 = s_sr[warp][j + 1];
            int s2 = s_sr[warp][j + 2], s3 = s_sr[warp][j + 3];
            const uint32_t* p0 = g_h2b + (size_t)s0 * 64;
            const uint32_t* p1 = g_h2b + (size_t)s1 * 64;
            const uint32_t* p2 = g_h2b + (size_t)s2 * 64;
            const uint32_t* p3 = g_h2b + (size_t)s3 * 64;
            uint32_t qa0 = p0[lane], qb0 = p0[lane + 32];
            uint32_t qa1 = p1[lane], qb1 = p1[lane + 32];
            uint32_t qa2 = p2[lane], qb2 = p2[lane + 32];
            uint32_t qa3 = p3[lane], qb3 = p3[lane + 32];
            float ea0 = s_ex[warp][j + 0][ha], eb0 = s_ex[warp][j + 0][hb];
            float ea1 = s_ex[warp][j + 1][ha], eb1 = s_ex[warp][j + 1][hb];
            float ea2 = s_ex[warp][j + 2][ha], eb2 = s_ex[warp][j + 2][hb];
            float ea3 = s_ex[warp][j + 3][ha], eb3 = s_ex[warp][j + 3][hb];
            float2 fa0 = __bfloat1622float2(*(__nv_bfloat162*)&qa0);
            float2 fb0 = __bfloat1622float2(*(__nv_bfloat162*)&qb0);
            float2 fa1 = __bfloat1622float2(*(__nv_bfloat162*)&qa1);
            float2 fb1 = __bfloat1622float2(*(__nv_bfloat162*)&qb1);
            float2 fa2 = __bfloat1622float2(*(__nv_bfloat162*)&qa2);
            float2 fb2 = __bfloat1622float2(*(__nv_bfloat162*)&qb2);
            float2 fa3 = __bfloat1622float2(*(__nv_bfloat162*)&qa3);
            float2 fb3 = __bfloat1622float2(*(__nv_bfloat162*)&qb3);
            a00 = fmaf(ea0, fa0.x, a00); a01 = fmaf(ea0, fa0.y, a01);
            a10 = fmaf(eb0, fb0.x, a10); a11 = fmaf(eb0, fb0.y, a11);
            a00 = fmaf(ea1, fa1.x, a00); a01 = fmaf(ea1, fa1.y, a01);
            a10 = fmaf(eb1, fb1.x, a10); a11 = fmaf(eb1, fb1.y, a11);
            a00 = fmaf(ea2, fa2.x, a00); a01 = fmaf(ea2, fa2.y, a01);
            a10 = fmaf(eb2, fb2.x, a10); a11 = fmaf(eb2, fb2.y, a11);
            a00 = fmaf(ea3, fa3.x, a00); a01 = fmaf(ea3, fa3.y, a01);
            a10 = fmaf(eb3, fb3.x, a10); a11 = fmaf(eb3, fb3.y, a11);
        }
        __syncwarp();
    }
#pragma unroll
    for (int k = 0; k < 8; k++)
#pragma unroll
        for (int off = 16; off; off >>= 1)
            den[k] += __shfl_xor_sync(0xffffffffu, den[k], off);

    float da = (lane < 8) ? den[0] : (lane < 16) ? den[1] : (lane < 24) ? den[2] : den[3];
    float db = (lane < 8) ? den[4] : (lane < 16) ? den[5] : (lane < 24) ? den[6] : den[7];
    float v0 = a00 / da + a10 / db;
    float v1 = a01 / da + a11 / db;
    v0 += __shfl_xor_sync(0xffffffffu, v0, 8);
    v0 += __shfl_xor_sync(0xffffffffu, v0, 16);
    v1 += __shfl_xor_sync(0xffffffffu, v1, 8);
    v1 += __shfl_xor_sync(0xffffffffu, v1, 16);
    int cp = lane & 7;
    v0 = v0 * 0.125f + bias2[2 * cp];
    v1 = v1 * 0.125f + bias2[2 * cp + 1];
    float mx = fmaxf(v0, v1);
#pragma unroll
    for (int off = 4; off; off >>= 1) mx = fmaxf(mx, __shfl_xor_sync(0xffffffffu, mx, off));
    float se = __expf(v0 - mx) + __expf(v1 - mx);
#pragma unroll
    for (int off = 4; off; off >>= 1) se += __shfl_xor_sync(0xffffffffu, se, off);
    float ls = __logf(se);
    if (lane < 8)
        *(float2*)(out + (size_t)n * 16 + 2 * cp) =
            make_float2(v0 - mx - ls, v1 - mx - ls);
}

// ---------------- launcher ------------------------------------------------------
extern "C" void kernel_launch(void* const* d_in, const int* in_sizes, int n_in,
                              void* d_out, int out_size) {
    const float* x   = (const float*)d_in[0];
    const int*   ei  = (const int*)d_in[1];
    const float* W1  = (const float*)d_in[2];
    const float* aS1 = (const float*)d_in[3];
    const float* aD1 = (const float*)d_in[4];
    const float* b1  = (const float*)d_in[5];
    const float* pw  = (const float*)d_in[6];
    const float* W2  = (const float*)d_in[7];
    const float* aS2 = (const float*)d_in[8];
    const float* aD2 = (const float*)d_in[9];
    const float* b2  = (const float*)d_in[10];
    float* out = (float*)d_out;

    const int* srcp = ei;
    const int* dstp = ei + EE;

    __nv_bfloat16 *p_w1h, *p_w2h, *p_o1h;
    cudaGetSymbolAddress((void**)&p_w1h, g_w1h);
    cudaGetSymbolAddress((void**)&p_w2h, g_w2h);
    cudaGetSymbolAddress((void**)&p_o1h, g_o1h);

    cudaFuncSetAttribute(k_gemm1_mma, cudaFuncAttributeMaxDynamicSharedMemorySize,
                         SM1_TOTAL);
    cudaFuncSetAttribute(k_gemm2_mma, cudaFuncAttributeMaxDynamicSharedMemorySize,
                         G2_TOTAL);

    // 1: prep (weights bf16 + counter resets)
    k_prep<<<(NN + 255) / 256, 256>>>(W1, W2);

    // fork: GEMM1 on side stream, split CSR build on default stream
    cudaEventRecord(g_ss.e0, 0);
    cudaStreamWaitEvent(g_ss.sA, g_ss.e0, 0);
    k_gemm1_mma<<<(NN + 255) / 256, 256, SM1_TOTAL, g_ss.sA>>>(x, p_w1h, aS1, aD1);
    cudaEventRecord(g_ss.eA, g_ss.sA);

    k_count<<<(EE / 4 + 255) / 256, 256>>>(dstp);
    k_scan_lb<<<98, 1024>>>();
    k_scatter<<<(EE / 4 + 255) / 256, 256>>>(srcp, dstp);

    // join, then pipelined agg1/gemm2 halves (agg kernels: default regs, no cap):
    cudaStreamWaitEvent(0, g_ss.eA, 0);
    k_agg1<<<HALF1 / 8, 256>>>(0, HALF1, b1, pw);                  // agg1_a
    cudaEventRecord(g_ss.eB, 0);
    k_agg1<<<(NN - HALF1 + 7) / 8, 256>>>(HALF1, NN, b1, pw);      // agg1_b
    // gemm2_a on side stream, concurrent with agg1_b
    cudaStreamWaitEvent(g_ss.sA, g_ss.eB, 0);
    k_gemm2_mma<<<HALF1 / 128, 256, G2_TOTAL, g_ss.sA>>>(0, HALF1, p_o1h, p_w2h,
                                                         aS2, aD2);
    cudaEventRecord(g_ss.eC, g_ss.sA);
    // gemm2_b on default stream (after agg1_b in program order)
    k_gemm2_mma<<<(NN - HALF1 + 127) / 128, 256, G2_TOTAL>>>(HALF1, NN, p_o1h,
                                                             p_w2h, aS2, aD2);
    cudaStreamWaitEvent(0, g_ss.eC, 0);
    k_agg2<<<(NN + 7) / 8, 256>>>(b2, out);
}

// round 17
// speedup vs baseline: 1.0915x; 1.0345x over previous
#include <cuda_runtime.h>
#include <cuda_bf16.h>
#include <cstdint>

#define NN 100000
#define EE 1600000
#define ETOT (EE + NN)

// ---------------- scratch (static __device__ — no allocations) ----------------
__device__ uint32_t g_h1b[NN * 32];   // h1 as packed bf16x2 (col pairs)
__device__ uint32_t g_h2b[NN * 64];   // h2 as packed bf16x2 (col pairs)
__device__ float g_as1[NN * 8];
__device__ float g_ad1[NN * 8];
__device__ float g_as2[NN * 8];
__device__ float g_ad2[NN * 8];
__device__ int   g_rowptr[NN + 1];
__device__ int   g_cur[NN];
__device__ int   g_csr[ETOT];
__device__ int   g_bagg[98];
__device__ int   g_cnt;
__device__ __nv_bfloat16 g_w1h[64 * 512];   // W1^T bf16 [n][k]
__device__ __nv_bfloat16 g_w2h[128 * 64];   // W2^T bf16 [n][k]
__device__ __nv_bfloat16 g_o1h[NN * 64];    // out1 bf16

// ---------------- streams/events (static init, before harness checkpoints) -----
struct SideStreams {
    cudaStream_t sA;
    cudaEvent_t e0, eA;
    SideStreams() {
        cudaStreamCreateWithFlags(&sA, cudaStreamNonBlocking);
        cudaEventCreateWithFlags(&e0, cudaEventDisableTiming);
        cudaEventCreateWithFlags(&eA, cudaEventDisableTiming);
    }
};
static SideStreams g_ss;

// ---------------- warp mma ------------------------------------------------------
__device__ __forceinline__ void mma16816(float* c, uint32_t a0, uint32_t a1,
                                         uint32_t a2, uint32_t a3,
                                         uint32_t b0, uint32_t b1) {
    asm volatile(
        "mma.sync.aligned.m16n8k16.row.col.f32.bf16.bf16.f32 "
        "{%0,%1,%2,%3}, {%4,%5,%6,%7}, {%8,%9}, {%0,%1,%2,%3};"
        : "+f"(c[0]), "+f"(c[1]), "+f"(c[2]), "+f"(c[3])
        : "r"(a0), "r"(a1), "r"(a2), "r"(a3), "r"(b0), "r"(b1));
}

// ---------------- prep: weight bf16 split + counter resets ----------------------
__global__ void k_prep(const float* __restrict__ W1, const float* __restrict__ W2) {
    int idx = blockIdx.x * 256 + threadIdx.x;
    if (idx < NN) g_cur[idx] = 0;
    if (idx == 0) g_cnt = 0;
    if (idx < 512 * 64) {
        int k = idx >> 6, n = idx & 63;
        g_w1h[n * 512 + k] = __float2bfloat16(W1[idx]);
    }
    if (idx < 64 * 128) {
        int k = idx >> 7, n = idx & 127;
        g_w2h[n * 64 + k] = __float2bfloat16(W2[idx]);
    }
}

// ---------------- CSR build (split kernels) -------------------------------------
__global__ void k_count(const int* __restrict__ dst) {
    int e4 = blockIdx.x * blockDim.x + threadIdx.x;
    if (e4 < EE / 4) {
        int4 d = *(const int4*)(dst + e4 * 4);
        atomicAdd(&g_cur[d.x], 1);
        atomicAdd(&g_cur[d.y], 1);
        atomicAdd(&g_cur[d.z], 1);
        atomicAdd(&g_cur[d.w], 1);
    }
}
__global__ void k_scan_lb() {
    __shared__ int sh[1024];
    __shared__ int s_excl;
    int t = threadIdx.x, bid = blockIdx.x;
    int i = bid * 1024 + t;
    int v = (i < NN) ? g_cur[i] + 1 : 0;  // +1 = self loop
    sh[t] = v;
    __syncthreads();
    for (int off = 1; off < 1024; off <<= 1) {
        int a = (t >= off) ? sh[t - off] : 0;
        __syncthreads();
        sh[t] += a;
        __syncthreads();
    }
    int incl = sh[t];
    if (t == 0) {
        g_bagg[bid] = sh[1023];
        __threadfence();
        atomicAdd(&g_cnt, 1);
        while (atomicAdd(&g_cnt, 0) < 98) { }
    }
    __syncthreads();
    if (t < 32) {
        int sum = 0;
        for (int base = 0; base < bid; base += 32) {
            int idx2 = base + t;
            int val = (idx2 < bid) ? g_bagg[idx2] : 0;
#pragma unroll
            for (int o = 16; o; o >>= 1) val += __shfl_xor_sync(0xffffffffu, val, o);
            sum += val;
        }
        if (t == 0) s_excl = sum;
    }
    __syncthreads();
    if (i < NN) {
        int p = s_excl + incl - v;
        g_rowptr[i] = p;
        g_csr[p] = i;
        g_cur[i] = p + 1;
    }
    if (i == 0) g_rowptr[NN] = ETOT;
}
__global__ void k_scatter(const int* __restrict__ src, const int* __restrict__ dst) {
    int e4 = blockIdx.x * blockDim.x + threadIdx.x;
    if (e4 < EE / 4) {
        int4 s = *(const int4*)(src + e4 * 4);
        int4 d = *(const int4*)(dst + e4 * 4);
        g_csr[atomicAdd(&g_cur[d.x], 1)] = s.x;
        g_csr[atomicAdd(&g_cur[d.y], 1)] = s.y;
        g_csr[atomicAdd(&g_cur[d.z], 1)] = s.z;
        g_csr[atomicAdd(&g_cur[d.w], 1)] = s.w;
    }
}

// ---------------- layer-1 GEMM via mma.sync (pure bf16), alpha fused ------------
#define A_OFF 0
#define B_OFF 36864
#define SM1_TOTAL 73728

__global__ void __launch_bounds__(256) k_gemm1_mma(
    const float* __restrict__ x, const __nv_bfloat16* __restrict__ Wh,
    const float* __restrict__ aS, const float* __restrict__ aD) {
    extern __shared__ char smem[];
    const int tid = threadIdx.x;
    const int wid = tid >> 5, lane = tid & 31;
    const int gr = lane >> 2;
    const int kc = (lane & 3) * 2;
    const int m0 = blockIdx.x * 256;
    const int wr = wid * 32;

    float acc[2][8][4];
#pragma unroll
    for (int i = 0; i < 2; i++)
#pragma unroll
        for (int j = 0; j < 8; j++)
#pragma unroll
            for (int q = 0; q < 4; q++) acc[i][j][q] = 0.f;

    for (int kt = 0; kt < 512; kt += 64) {
#pragma unroll
        for (int i = 0; i < 16; i++) {
            int idx = tid + 256 * i;
            int r = idx >> 4, c4 = idx & 15;
            float4 v = make_float4(0.f, 0.f, 0.f, 0.f);
            if (m0 + r < NN)
                v = *(const float4*)(x + (size_t)(m0 + r) * 512 + kt + c4 * 4);
            __nv_bfloat162 h01 = __floats2bfloat162_rn(v.x, v.y);
            __nv_bfloat162 h23 = __floats2bfloat162_rn(v.z, v.w);
            *(uint2*)(smem + A_OFF + r * 144 + c4 * 8) =
                make_uint2(*(uint32_t*)&h01, *(uint32_t*)&h23);
        }
#pragma unroll
        for (int i = 0; i < 4; i++) {
            int idx = tid + 256 * i;
            int n = idx >> 4, c4 = idx & 15;
            *(uint2*)(smem + B_OFF + n * 144 + c4 * 8) =
                *(const uint2*)(Wh + n * 512 + kt + c4 * 4);
        }
        __syncthreads();
#pragma unroll
        for (int s = 0; s < 4; s++) {
            const int ks = s * 16;
            uint32_t ar[2][4];
#pragma unroll
            for (int i = 0; i < 2; i++) {
                int r0 = wr + i * 16 + gr;
                const char* pa = smem + A_OFF + (r0 * 144 + (ks + kc) * 2);
                ar[i][0] = *(const uint32_t*)(pa);
                ar[i][1] = *(const uint32_t*)(pa + 8 * 144);
                ar[i][2] = *(const uint32_t*)(pa + 16);
                ar[i][3] = *(const uint32_t*)(pa + 8 * 144 + 16);
            }
#pragma unroll
            for (int j = 0; j < 8; j++) {
                int n0 = j * 8 + gr;
                const char* pb = smem + B_OFF + (n0 * 144 + (ks + kc) * 2);
                uint32_t b0 = *(const uint32_t*)(pb);
                uint32_t b1 = *(const uint32_t*)(pb + 16);
#pragma unroll
                for (int i = 0; i < 2; i++)
                    mma16816(acc[i][j], ar[i][0], ar[i][1], ar[i][2], ar[i][3], b0, b1);
            }
        }
        __syncthreads();
    }

    float* Cs = (float*)smem;
#pragma unroll
    for (int i = 0; i < 2; i++) {
        int r0 = wr + i * 16 + gr;
#pragma unroll
        for (int j = 0; j < 8; j++) {
            int col = j * 8 + kc;
            *(float2*)&Cs[r0 * 72 + col] = make_float2(acc[i][j][0], acc[i][j][1]);
            *(float2*)&Cs[(r0 + 8) * 72 + col] = make_float2(acc[i][j][2], acc[i][j][3]);
        }
    }
    __syncthreads();

    int m = m0 + tid;
    if (m < NN) {
        const float* row = Cs + tid * 72;
#pragma unroll
        for (int c = 0; c < 64; c += 8) {
            __nv_bfloat162 t0 = __floats2bfloat162_rn(row[c + 0], row[c + 1]);
            __nv_bfloat162 t1 = __floats2bfloat162_rn(row[c + 2], row[c + 3]);
            __nv_bfloat162 t2 = __floats2bfloat162_rn(row[c + 4], row[c + 5]);
            __nv_bfloat162 t3 = __floats2bfloat162_rn(row[c + 6], row[c + 7]);
            *(uint4*)(g_h1b + (size_t)m * 32 + c / 2) =
                make_uint4(*(uint32_t*)&t0, *(uint32_t*)&t1,
                           *(uint32_t*)&t2, *(uint32_t*)&t3);
        }
        float s[8], t[8];
#pragma unroll
        for (int h = 0; h < 8; h++) { s[h] = 0.f; t[h] = 0.f; }
#pragma unroll
        for (int h = 0; h < 8; h++)
#pragma unroll
            for (int c = 0; c < 8; c++) {
                float v = row[h * 8 + c];
                s[h] = fmaf(v, aS[h * 8 + c], s[h]);
                t[h] = fmaf(v, aD[h * 8 + c], t[h]);
            }
        *(float4*)(g_as1 + (size_t)m * 8) = make_float4(s[0], s[1], s[2], s[3]);
        *(float4*)(g_as1 + (size_t)m * 8 + 4) = make_float4(s[4], s[5], s[6], s[7]);
        *(float4*)(g_ad1 + (size_t)m * 8) = make_float4(t[0], t[1], t[2], t[3]);
        *(float4*)(g_ad1 + (size_t)m * 8 + 4) = make_float4(t[4], t[5], t[6], t[7]);
    }
}

// ---------------- layer-2 GEMM via mma.sync (pure bf16), alpha fused ------------
#define G2_A 0
#define G2_B 18432
#define G2_TOTAL 67584

__global__ void __launch_bounds__(256) k_gemm2_mma(
    const __nv_bfloat16* __restrict__ Ah, const __nv_bfloat16* __restrict__ Bh,
    const float* __restrict__ aS, const float* __restrict__ aD) {
    extern __shared__ char smem[];
    const int tid = threadIdx.x;
    const int wid = tid >> 5, lane = tid & 31;
    const int gr = lane >> 2;
    const int kc = (lane & 3) * 2;
    const int wm = wid & 3, wn = wid >> 2;
    const int m0 = blockIdx.x * 128;

#pragma unroll
    for (int i = 0; i < 8; i++) {
        int idx = tid + 256 * i;
        int r = idx >> 4, c4 = idx & 15;
        uint2 vh = make_uint2(0u, 0u);
        if (m0 + r < NN)
            vh = *(const uint2*)(Ah + (size_t)(m0 + r) * 64 + c4 * 4);
        *(uint2*)(smem + G2_A + r * 144 + c4 * 8) = vh;
    }
#pragma unroll
    for (int i = 0; i < 8; i++) {
        int idx = tid + 256 * i;
        int n = idx >> 4, c4 = idx & 15;
        *(uint2*)(smem + G2_B + n * 144 + c4 * 8) =
            *(const uint2*)(Bh + n * 64 + c4 * 4);
    }
    __syncthreads();

    float acc[2][8][4];
#pragma unroll
    for (int i = 0; i < 2; i++)
#pragma unroll
        for (int j = 0; j < 8; j++)
#pragma unroll
            for (int q = 0; q < 4; q++) acc[i][j][q] = 0.f;

#pragma unroll
    for (int s = 0; s < 4; s++) {
        const int ks = s * 16;
        uint32_t ar[2][4];
#pragma unroll
        for (int i = 0; i < 2; i++) {
            int r0 = wm * 32 + i * 16 + gr;
            const char* pa = smem + G2_A + (r0 * 144 + (ks + kc) * 2);
            ar[i][0] = *(const uint32_t*)(pa);
            ar[i][1] = *(const uint32_t*)(pa + 8 * 144);
            ar[i][2] = *(const uint32_t*)(pa + 16);
            ar[i][3] = *(const uint32_t*)(pa + 8 * 144 + 16);
        }
#pragma unroll
        for (int j = 0; j < 8; j++) {
            int n0 = wn * 64 + j * 8 + gr;
            const char* pb = smem + G2_B + (n0 * 144 + (ks + kc) * 2);
            uint32_t b0 = *(const uint32_t*)(pb);
            uint32_t b1 = *(const uint32_t*)(pb + 16);
#pragma unroll
            for (int i = 0; i < 2; i++)
                mma16816(acc[i][j], ar[i][0], ar[i][1], ar[i][2], ar[i][3], b0, b1);
        }
    }
    __syncthreads();

    float* Cs = (float*)smem;
#pragma unroll
    for (int i = 0; i < 2; i++) {
        int r0 = wm * 32 + i * 16 + gr;
#pragma unroll
        for (int j = 0; j < 8; j++) {
            int col = wn * 64 + j * 8 + kc;
            *(float2*)&Cs[r0 * 132 + col] = make_float2(acc[i][j][0], acc[i][j][1]);
            *(float2*)&Cs[(r0 + 8) * 132 + col] = make_float2(acc[i][j][2], acc[i][j][3]);
        }
    }
    __syncthreads();

    int r = tid >> 1, chalf = (tid & 1) * 64;
    int m = m0 + r;
    if (m < NN) {
        const float* row = Cs + r * 132 + chalf;
#pragma unroll
        for (int c = 0; c < 64; c += 8) {
            __nv_bfloat162 t0 = __floats2bfloat162_rn(row[c + 0], row[c + 1]);
            __nv_bfloat162 t1 = __floats2bfloat162_rn(row[c + 2], row[c + 3]);
            __nv_bfloat162 t2 = __floats2bfloat162_rn(row[c + 4], row[c + 5]);
            __nv_bfloat162 t3 = __floats2bfloat162_rn(row[c + 6], row[c + 7]);
            *(uint4*)(g_h2b + (size_t)m * 64 + (tid & 1) * 32 + c / 2) =
                make_uint4(*(uint32_t*)&t0, *(uint32_t*)&t1,
                           *(uint32_t*)&t2, *(uint32_t*)&t3);
        }
        int hb = (tid & 1) * 4;
        float s[4], t[4];
#pragma unroll
        for (int q = 0; q < 4; q++) { s[q] = 0.f; t[q] = 0.f; }
#pragma unroll
        for (int q = 0; q < 4; q++) {
            int hh = hb + q;
#pragma unroll
            for (int c = 0; c < 16; c++) {
                float v = row[q * 16 + c];
                s[q] = fmaf(v, aS[hh * 16 + c], s[q]);
                t[q] = fmaf(v, aD[hh * 16 + c], t[q]);
            }
        }
        *(float4*)(g_as2 + (size_t)m * 8 + hb) = make_float4(s[0], s[1], s[2], s[3]);
        *(float4*)(g_ad2 + (size_t)m * 8 + hb) = make_float4(t[0], t[1], t[2], t[3]);
    }
}

// ---------------- layer-1 aggregation (den accumulated in j-loop) ---------------
__global__ void __launch_bounds__(256) k_agg1(
    const float* __restrict__ bias, const float* __restrict__ preluw) {
    __shared__ float s_ex[8][32][8];
    __shared__ int s_sr[8][32];
    int warp = threadIdx.x >> 5, lane = threadIdx.x & 31;
    int n = blockIdx.x * 8 + warp;
    if (n >= NN) return;
    int s = g_rowptr[n], e2 = g_rowptr[n + 1];

    float adv[8];
    {
        float4 a0 = *(const float4*)(g_ad1 + n * 8);
        float4 a1 = *(const float4*)(g_ad1 + n * 8 + 4);
        adv[0] = a0.x; adv[1] = a0.y; adv[2] = a0.z; adv[3] = a0.w;
        adv[4] = a1.x; adv[5] = a1.y; adv[6] = a1.z; adv[7] = a1.w;
    }
    float den_own = 0.f;           // per-lane: sum of ex for its own head over ALL edges
    float a0c = 0.f, a1c = 0.f;
    const int hown = lane >> 2;
    for (int base = s; base < e2; base += 32) {
        int idx = base + lane;
        int cnt = min(32, e2 - base);
        int sr = 0;
        float ex[8];
#pragma unroll
        for (int k = 0; k < 8; k++) ex[k] = 0.f;
        if (idx < e2) {
            sr = g_csr[idx];
            float4 a0 = *(const float4*)(g_as1 + sr * 8);
            float4 a1 = *(const float4*)(g_as1 + sr * 8 + 4);
            float av[8] = {a0.x, a0.y, a0.z, a0.w, a1.x, a1.y, a1.z, a1.w};
#pragma unroll
            for (int k = 0; k < 8; k++) {
                float e = av[k] + adv[k];
                e = e >= 0.f ? e : 0.2f * e;
                ex[k] = __expf(e);
            }
        }
        s_sr[warp][lane] = sr;
        *(float4*)&s_ex[warp][lane][0] = make_float4(ex[0], ex[1], ex[2], ex[3]);
        *(float4*)&s_ex[warp][lane][4] = make_float4(ex[4], ex[5], ex[6], ex[7]);
        __syncwarp();
        int cnt4 = (cnt + 3) & ~3;
        for (int j = 0; j < cnt4; j += 4) {
            int s0 = s_sr[warp][j + 0], s1 = s_sr[warp][j + 1];
            int s2 = s_sr[warp][j + 2], s3 = s_sr[warp][j + 3];
            uint32_t q0 = g_h1b[(size_t)s0 * 32 + lane];
            uint32_t q1 = g_h1b[(size_t)s1 * 32 + lane];
            uint32_t q2 = g_h1b[(size_t)s2 * 32 + lane];
            uint32_t q3 = g_h1b[(size_t)s3 * 32 + lane];
            float e0 = s_ex[warp][j + 0][hown];
            float e1 = s_ex[warp][j + 1][hown];
            float e2w = s_ex[warp][j + 2][hown];
            float e3 = s_ex[warp][j + 3][hown];
            den_own += (e0 + e1) + (e2w + e3);
            float2 f0 = __bfloat1622float2(*(__nv_bfloat162*)&q0);
            float2 f1 = __bfloat1622float2(*(__nv_bfloat162*)&q1);
            float2 f2 = __bfloat1622float2(*(__nv_bfloat162*)&q2);
            float2 f3 = __bfloat1622float2(*(__nv_bfloat162*)&q3);
            a0c = fmaf(e0, f0.x, a0c); a1c = fmaf(e0, f0.y, a1c);
            a0c = fmaf(e1, f1.x, a0c); a1c = fmaf(e1, f1.y, a1c);
            a0c = fmaf(e2w, f2.x, a0c); a1c = fmaf(e2w, f2.y, a1c);
            a0c = fmaf(e3, f3.x, a0c); a1c = fmaf(e3, f3.y, a1c);
        }
        __syncwarp();
    }

    float pw = *preluw;
    float v0 = a0c / den_own + bias[2 * lane];
    float v1 = a1c / den_own + bias[2 * lane + 1];
    v0 = v0 >= 0.f ? v0 : pw * v0;
    v1 = v1 >= 0.f ? v1 : pw * v1;
    __nv_bfloat162 hi = __floats2bfloat162_rn(v0, v1);
    ((uint32_t*)(g_o1h + (size_t)n * 64))[lane] = *(uint32_t*)&hi;
}

// ---------------- layer-2 aggregation (den in j-loop) + mean + log_softmax ------
__global__ void __launch_bounds__(256) k_agg2(
    const float* __restrict__ bias2, float* __restrict__ out) {
    __shared__ float s_ex[8][32][8];
    __shared__ int s_sr[8][32];
    int warp = threadIdx.x >> 5, lane = threadIdx.x & 31;
    int n = blockIdx.x * 8 + warp;
    if (n >= NN) return;
    int s = g_rowptr[n], e2 = g_rowptr[n + 1];

    float adv[8];
    {
        float4 a0 = *(const float4*)(g_ad2 + n * 8);
        float4 a1 = *(const float4*)(g_ad2 + n * 8 + 4);
        adv[0] = a0.x; adv[1] = a0.y; adv[2] = a0.z; adv[3] = a0.w;
        adv[4] = a1.x; adv[5] = a1.y; adv[6] = a1.z; adv[7] = a1.w;
    }
    float dena = 0.f, denb = 0.f;  // per-lane denominators for its two heads
    float a00 = 0.f, a01 = 0.f, a10 = 0.f, a11 = 0.f;
    const int ha = lane >> 3, hb = 4 + (lane >> 3);
    for (int base = s; base < e2; base += 32) {
        int idx = base + lane;
        int cnt = min(32, e2 - base);
        int sr = 0;
        float ex[8];
#pragma unroll
        for (int k = 0; k < 8; k++) ex[k] = 0.f;
        if (idx < e2) {
            sr = g_csr[idx];
            float4 a0 = *(const float4*)(g_as2 + sr * 8);
            float4 a1 = *(const float4*)(g_as2 + sr * 8 + 4);
            float av[8] = {a0.x, a0.y, a0.z, a0.w, a1.x, a1.y, a1.z, a1.w};
#pragma unroll
            for (int k = 0; k < 8; k++) {
                float e = av[k] + adv[k];
                e = e >= 0.f ? e : 0.2f * e;
                ex[k] = __expf(e);
            }
        }
        s_sr[warp][lane] = sr;
        *(float4*)&s_ex[warp][lane][0] = make_float4(ex[0], ex[1], ex[2], ex[3]);
        *(float4*)&s_ex[warp][lane][4] = make_float4(ex[4], ex[5], ex[6], ex[7]);
        __syncwarp();
        int cnt4 = (cnt + 3) & ~3;
        for (int j = 0; j < cnt4; j += 4) {
            int s0 = s_sr[warp][j + 0], s1 = s_sr[warp][j + 1];
            int s2 = s_sr[warp][j + 2], s3 = s_sr[warp][j + 3];
            const uint32_t* p0 = g_h2b + (size_t)s0 * 64;
            const uint32_t* p1 = g_h2b + (size_t)s1 * 64;
            const uint32_t* p2 = g_h2b + (size_t)s2 * 64;
            const uint32_t* p3 = g_h2b + (size_t)s3 * 64;
            uint32_t qa0 = p0[lane], qb0 = p0[lane + 32];
            uint32_t qa1 = p1[lane], qb1 = p1[lane + 32];
            uint32_t qa2 = p2[lane], qb2 = p2[lane + 32];
            uint32_t qa3 = p3[lane], qb3 = p3[lane + 32];
            float ea0 = s_ex[warp][j + 0][ha], eb0 = s_ex[warp][j + 0][hb];
            float ea1 = s_ex[warp][j + 1][ha], eb1 = s_ex[warp][j + 1][hb];
            float ea2 = s_ex[warp][j + 2][ha], eb2 = s_ex[warp][j + 2][hb];
            float ea3 = s_ex[warp][j + 3][ha], eb3 = s_ex[warp][j + 3][hb];
            dena += (ea0 + ea1) + (ea2 + ea3);
            denb += (eb0 + eb1) + (eb2 + eb3);
            float2 fa0 = __bfloat1622float2(*(__nv_bfloat162*)&qa0);
            float2 fb0 = __bfloat1622float2(*(__nv_bfloat162*)&qb0);
            float2 fa1 = __bfloat1622float2(*(__nv_bfloat162*)&qa1);
            float2 fb1 = __bfloat1622float2(*(__nv_bfloat162*)&qb1);
            float2 fa2 = __bfloat1622float2(*(__nv_bfloat162*)&qa2);
            float2 fb2 = __bfloat1622float2(*(__nv_bfloat162*)&qb2);
            float2 fa3 = __bfloat1622float2(*(__nv_bfloat162*)&qa3);
            float2 fb3 = __bfloat1622float2(*(__nv_bfloat162*)&qb3);
            a00 = fmaf(ea0, fa0.x, a00); a01 = fmaf(ea0, fa0.y, a01);
            a10 = fmaf(eb0, fb0.x, a10); a11 = fmaf(eb0, fb0.y, a11);
            a00 = fmaf(ea1, fa1.x, a00); a01 = fmaf(ea1, fa1.y, a01);
            a10 = fmaf(eb1, fb1.x, a10); a11 = fmaf(eb1, fb1.y, a11);
            a00 = fmaf(ea2, fa2.x, a00); a01 = fmaf(ea2, fa2.y, a01);
            a10 = fmaf(eb2, fb2.x, a10); a11 = fmaf(eb2, fb2.y, a11);
            a00 = fmaf(ea3, fa3.x, a00); a01 = fmaf(ea3, fa3.y, a01);
            a10 = fmaf(eb3, fb3.x, a10); a11 = fmaf(eb3, fb3.y, a11);
        }
        __syncwarp();
    }

    float v0 = a00 / dena + a10 / denb;
    float v1 = a01 / dena + a11 / denb;
    v0 += __shfl_xor_sync(0xffffffffu, v0, 8);
    v0 += __shfl_xor_sync(0xffffffffu, v0, 16);
    v1 += __shfl_xor_sync(0xffffffffu, v1, 8);
    v1 += __shfl_xor_sync(0xffffffffu, v1, 16);
    int cp = lane & 7;
    v0 = v0 * 0.125f + bias2[2 * cp];
    v1 = v1 * 0.125f + bias2[2 * cp + 1];
    float mx = fmaxf(v0, v1);
#pragma unroll
    for (int off = 4; off; off >>= 1) mx = fmaxf(mx, __shfl_xor_sync(0xffffffffu, mx, off));
    float se = __expf(v0 - mx) + __expf(v1 - mx);
#pragma unroll
    for (int off = 4; off; off >>= 1) se += __shfl_xor_sync(0xffffffffu, se, off);
    float ls = __logf(se);
    if (lane < 8)
        *(float2*)(out + (size_t)n * 16 + 2 * cp) =
            make_float2(v0 - mx - ls, v1 - mx - ls);
}

// ---------------- launcher ------------------------------------------------------
extern "C" void kernel_launch(void* const* d_in, const int* in_sizes, int n_in,
                              void* d_out, int out_size) {
    const float* x   = (const float*)d_in[0];
    const int*   ei  = (const int*)d_in[1];
    const float* W1  = (const float*)d_in[2];
    const float* aS1 = (const float*)d_in[3];
    const float* aD1 = (const float*)d_in[4];
    const float* b1  = (const float*)d_in[5];
    const float* pw  = (const float*)d_in[6];
    const float* W2  = (const float*)d_in[7];
    const float* aS2 = (const float*)d_in[8];
    const float* aD2 = (const float*)d_in[9];
    const float* b2  = (const float*)d_in[10];
    float* out = (float*)d_out;

    const int* srcp = ei;
    const int* dstp = ei + EE;

    __nv_bfloat16 *p_w1h, *p_w2h, *p_o1h;
    cudaGetSymbolAddress((void**)&p_w1h, g_w1h);
    cudaGetSymbolAddress((void**)&p_w2h, g_w2h);
    cudaGetSymbolAddress((void**)&p_o1h, g_o1h);

    cudaFuncSetAttribute(k_gemm1_mma, cudaFuncAttributeMaxDynamicSharedMemorySize,
                         SM1_TOTAL);
    cudaFuncSetAttribute(k_gemm2_mma, cudaFuncAttributeMaxDynamicSharedMemorySize,
                         G2_TOTAL);

    // 1: prep (weights bf16 + counter resets)
    k_prep<<<(NN + 255) / 256, 256>>>(W1, W2);

    // fork: GEMM1 on side stream, split CSR build on default stream
    cudaEventRecord(g_ss.e0, 0);
    cudaStreamWaitEvent(g_ss.sA, g_ss.e0, 0);
    k_gemm1_mma<<<(NN + 255) / 256, 256, SM1_TOTAL, g_ss.sA>>>(x, p_w1h, aS1, aD1);
    cudaEventRecord(g_ss.eA, g_ss.sA);

    k_count<<<(EE / 4 + 255) / 256, 256>>>(dstp);
    k_scan_lb<<<98, 1024>>>();
    k_scatter<<<(EE / 4 + 255) / 256, 256>>>(srcp, dstp);

    // join: aggregation tail (non-pipelined — pipeline measured neutral)
    cudaStreamWaitEvent(0, g_ss.eA, 0);
    k_agg1<<<(NN + 7) / 8, 256>>>(b1, pw);
    k_gemm2_mma<<<(NN + 127) / 128, 256, G2_TOTAL>>>(p_o1h, p_w2h, aS2, aD2);
    k_agg2<<<(NN + 7) / 8, 256>>>(b2, out);
}